// round 16
// baseline (speedup 1.0000x reference)
#include <cuda_runtime.h>

#define B_    64
#define CIN   64
#define T_    300
#define N_    25
#define COUT  128
#define EMB   32
#define KV    3
#define NCHUNK 12
#define TCHUNK 25
#define NPAD  28      // padded joint dim (16B-aligned rows)
#define EWPAD 65      // padded weight row (bank-conflict-free)
#define WPAD  129     // padded transposed-weight row in kernC
#define TT    5       // t's per block in kernC

typedef unsigned long long u64;

// scratch (static device globals; no allocation allowed)
__device__ float g_Spart[B_ * NCHUNK * N_ * N_];
__device__ float g_adj[B_ * N_ * N_];

__device__ __forceinline__ void fma2(u64& d, u64 a, u64 b) {
    asm("fma.rn.f32x2 %0, %1, %2, %0;" : "+l"(d) : "l"(a), "l"(b));
}
__device__ __forceinline__ u64 pack2(float x, float y) {
    u64 r; asm("mov.b64 %0, {%1, %2};" : "=l"(r) : "f"(x), "f"(y)); return r;
}
__device__ __forceinline__ float2 unpack2(u64 v) {
    float2 r; asm("mov.b64 {%0, %1}, %2;" : "=f"(r.x), "=f"(r.y) : "l"(v)); return r;
}

// ---------------------------------------------------------------------------
// Kernel A: embeddings theta/phi per t, accumulate partial S = sum_t Th^T Ph
// grid (NCHUNK, B_), 256 threads
// ---------------------------------------------------------------------------
__global__ __launch_bounds__(256) void kernA(
    const float* __restrict__ x,
    const float* __restrict__ thw, const float* __restrict__ thb,
    const float* __restrict__ phw, const float* __restrict__ phb)
{
    __shared__ __align__(16) float tws[EMB * EWPAD];
    __shared__ __align__(16) float pws[EMB * EWPAD];
    __shared__ float tbs[EMB], pbs[EMB];
    __shared__ __align__(16) float xt[CIN * NPAD];
    __shared__ __align__(16) float th[EMB * NPAD];
    __shared__ __align__(16) float ph[EMB * NPAD];

    const int tid = threadIdx.x;
    const int ci = blockIdx.x, b = blockIdx.y;

    for (int i = tid; i < EMB * CIN; i += 256) {
        int e = i >> 6, c = i & 63;
        tws[e * EWPAD + c] = thw[i];
        pws[e * EWPAD + c] = phw[i];
    }
    if (tid < EMB) { tbs[tid] = thb[tid]; pbs[tid] = phb[tid]; }

    // S item: (n, g) with m = 4g..4g+3
    const int sn = tid / 7, sg = tid % 7;
    const bool sact = tid < (N_ * 7);              // 175
    u64 s0 = 0, s1 = 0;

    // embed item: (e, g) covering n = 4g..4g+3, computes both th and ph
    const int ee = tid / 7, eg = tid % 7;
    const bool eact = tid < (EMB * 7);             // 224

    __syncthreads();

    for (int ti = 0; ti < TCHUNK; ++ti) {
        const int t = ci * TCHUNK + ti;
        for (int i = tid; i < CIN * NPAD; i += 256) {
            int c = i / NPAD, n = i % NPAD;
            xt[i] = (n < N_) ? x[((b * CIN + c) * T_ + t) * N_ + n] : 0.f;
        }
        __syncthreads();

        if (eact) {
            u64 a0 = pack2(tbs[ee], tbs[ee]);
            u64 a1 = a0;
            u64 p0 = pack2(pbs[ee], pbs[ee]);
            u64 p1 = p0;
            const float* twr = tws + ee * EWPAD;
            const float* pwr = pws + ee * EWPAD;
            #pragma unroll 4
            for (int c = 0; c < CIN; ++c) {
                ulonglong2 xq = *(const ulonglong2*)(xt + c * NPAD + eg * 4);
                float wt = twr[c], wp = pwr[c];
                u64 wtp = pack2(wt, wt), wpp = pack2(wp, wp);
                fma2(a0, wtp, xq.x); fma2(a1, wtp, xq.y);
                fma2(p0, wpp, xq.x); fma2(p1, wpp, xq.y);
            }
            ulonglong2 ta; ta.x = a0; ta.y = a1;
            *(ulonglong2*)(th + ee * NPAD + eg * 4) = ta;
            ulonglong2 pa; pa.x = p0; pa.y = p1;
            *(ulonglong2*)(ph + ee * NPAD + eg * 4) = pa;
        }
        __syncthreads();

        if (sact) {
            #pragma unroll 4
            for (int e = 0; e < EMB; ++e) {
                float tv = th[e * NPAD + sn];
                u64 tp = pack2(tv, tv);
                ulonglong2 pq = *(const ulonglong2*)(ph + e * NPAD + sg * 4);
                fma2(s0, tp, pq.x); fma2(s1, tp, pq.y);
            }
        }
        __syncthreads();
    }

    if (sact) {
        float* dst = g_Spart + ((b * NCHUNK + ci) * N_ + sn) * N_;
        float2 v0 = unpack2(s0), v1 = unpack2(s1);
        int m0 = sg * 4;
        dst[m0] = v0.x;
        if (m0 + 1 < N_) dst[m0 + 1] = v0.y;
        if (m0 + 2 < N_) dst[m0 + 2] = v1.x;
        if (m0 + 3 < N_) dst[m0 + 3] = v1.y;
    }
}

// ---------------------------------------------------------------------------
// Kernel B: reduce partials, softmax rows, adj = sum_k(A+B) + KV*softmax
// grid B_, 32 threads (25 active; one thread per row)
// ---------------------------------------------------------------------------
__global__ void kernB(const float* __restrict__ Bp, const float* __restrict__ A)
{
    const int b = blockIdx.x, n = threadIdx.x;
    if (n >= N_) return;
    float row[N_];
    #pragma unroll
    for (int m = 0; m < N_; ++m) {
        float s = 0.f;
        #pragma unroll
        for (int ci = 0; ci < NCHUNK; ++ci)
            s += g_Spart[((b * NCHUNK + ci) * N_ + n) * N_ + m];
        row[m] = s;
    }
    float mx = row[0];
    #pragma unroll
    for (int m = 1; m < N_; ++m) mx = fmaxf(mx, row[m]);
    float den = 0.f;
    #pragma unroll
    for (int m = 0; m < N_; ++m) { row[m] = expf(row[m] - mx); den += row[m]; }
    float inv = (float)KV / den;
    #pragma unroll
    for (int m = 0; m < N_; ++m) {
        float st = 0.f;
        #pragma unroll
        for (int k = 0; k < KV; ++k)
            st += A[(k * N_ + n) * N_ + m] + Bp[(k * N_ + n) * N_ + m];
        g_adj[(b * N_ + n) * N_ + m] = st + row[m] * inv;
    }
}

// ---------------------------------------------------------------------------
// Kernel C: y = X*adj ; out = relu(BN(W1*y + Wr*x + b1 + br))
// grid (T_/TT, B_), 128 threads (thread = output channel o), 83KB dyn smem
// ---------------------------------------------------------------------------
__global__ __launch_bounds__(128) void kernC(
    const float* __restrict__ x,
    const float* __restrict__ w1, const float* __restrict__ b1,
    const float* __restrict__ wr, const float* __restrict__ br,
    const float* __restrict__ gamma, const float* __restrict__ beta,
    const float* __restrict__ rmean, const float* __restrict__ rvar,
    float* __restrict__ out)
{
    extern __shared__ __align__(16) float sm[];
    float* w1s  = sm;                       // CIN*WPAD (transposed, padded)
    float* wrs  = w1s + CIN * WPAD;         // CIN*WPAD
    float* adjs = wrs + CIN * WPAD;         // N_*NPAD
    float* xs   = adjs + N_ * NPAD;         // CIN*NPAD
    float* ys   = xs + CIN * NPAD;          // CIN*NPAD

    const int tid = threadIdx.x;
    const int b = blockIdx.y;
    const int t0 = blockIdx.x * TT;

    for (int i = tid; i < COUT * CIN; i += 128) {
        int o = i >> 6, c = i & 63;
        w1s[c * WPAD + o] = w1[i];
        wrs[c * WPAD + o] = wr[i];
    }
    for (int i = tid; i < N_ * NPAD; i += 128) {
        int n = i / NPAD, m = i % NPAD;
        adjs[i] = (m < N_) ? g_adj[(b * N_ + n) * N_ + m] : 0.f;
    }
    const int o = tid;
    const float sc = gamma[o] * rsqrtf(rvar[o] + 1e-5f);
    const float sh = beta[o] - rmean[o] * sc;
    const float bias = b1[o] + br[o];
    const u64 bias2 = pack2(bias, bias);
    const float* xb = x + (size_t)b * CIN * T_ * N_;
    __syncthreads();

    for (int tt = 0; tt < TT; ++tt) {
        const int t = t0 + tt;
        // load x tile (padded rows, zero pad)
        for (int i = tid; i < CIN * NPAD; i += 128) {
            int c = i / NPAD, n = i % NPAD;
            xs[i] = (n < N_) ? xb[(c * T_ + t) * N_ + n] : 0.f;
        }
        __syncthreads();
        // y[c][m] = sum_n x[c][n] * adj[n][m]   (f32x2 over m-pairs)
        for (int it = tid; it < CIN * 7; it += 128) {
            int c = it / 7, g = it % 7;
            u64 a0 = 0, a1 = 0;
            const float* xr = xs + c * NPAD;
            const float* ar = adjs + g * 4;
            #pragma unroll
            for (int n = 0; n < N_; ++n) {
                float xv = xr[n];
                u64 xp = pack2(xv, xv);
                ulonglong2 av = *(const ulonglong2*)(ar + n * NPAD);
                fma2(a0, xp, av.x); fma2(a1, xp, av.y);
            }
            ulonglong2 w; w.x = a0; w.y = a1;
            *(ulonglong2*)(ys + c * NPAD + g * 4) = w;
        }
        __syncthreads();
        // main: 25 accumulators (14 f32x2 pairs, pads are zero)
        u64 acc[14];
        #pragma unroll
        for (int j = 0; j < 14; ++j) acc[j] = bias2;
        const float* w1c = w1s + o;
        const float* wrc = wrs + o;
        #pragma unroll 2
        for (int c = 0; c < CIN; ++c) {
            float wa = w1c[c * WPAD], wb = wrc[c * WPAD];
            u64 wap = pack2(wa, wa), wbp = pack2(wb, wb);
            const ulonglong2* yr = (const ulonglong2*)(ys + c * NPAD);
            const ulonglong2* xr = (const ulonglong2*)(xs + c * NPAD);
            #pragma unroll
            for (int q = 0; q < 7; ++q) {
                ulonglong2 yv = yr[q];
                ulonglong2 xv = xr[q];
                fma2(acc[2 * q],     wap, yv.x);
                fma2(acc[2 * q + 1], wap, yv.y);
                fma2(acc[2 * q],     wbp, xv.x);
                fma2(acc[2 * q + 1], wbp, xv.y);
            }
        }
        __syncthreads();
        // epilogue: BN + ReLU, stage in smem (reuse xs/ys), coalesced store
        float* outs = xs;
        #pragma unroll
        for (int j = 0; j < 13; ++j) {
            float2 v = unpack2(acc[j]);
            int m0 = 2 * j;
            outs[o * 26 + m0] = fmaxf(fmaf(v.x, sc, sh), 0.f);
            if (m0 + 1 < N_)
                outs[o * 26 + m0 + 1] = fmaxf(fmaf(v.y, sc, sh), 0.f);
        }
        __syncthreads();
        for (int i = tid; i < COUT * N_; i += 128) {
            int oo = i / N_, nn = i % N_;
            out[((size_t)(b * COUT + oo) * T_ + t) * N_ + nn] = outs[oo * 26 + nn];
        }
        __syncthreads();
    }
}

// ---------------------------------------------------------------------------
extern "C" void kernel_launch(void* const* d_in, const int* in_sizes, int n_in,
                              void* d_out, int out_size)
{
    const float* x   = (const float*)d_in[0];
    const float* thw = (const float*)d_in[1];
    const float* thb = (const float*)d_in[2];
    const float* phw = (const float*)d_in[3];
    const float* phb = (const float*)d_in[4];
    const float* Bp  = (const float*)d_in[5];
    const float* A   = (const float*)d_in[6];
    const float* w1  = (const float*)d_in[7];
    const float* b1  = (const float*)d_in[8];
    const float* wr  = (const float*)d_in[9];
    const float* br  = (const float*)d_in[10];
    const float* ga  = (const float*)d_in[11];
    const float* be  = (const float*)d_in[12];
    const float* rm  = (const float*)d_in[13];
    const float* rv  = (const float*)d_in[14];
    float* out = (float*)d_out;

    const int smemC = (2 * CIN * WPAD + N_ * NPAD + 2 * CIN * NPAD) * (int)sizeof(float);
    cudaFuncSetAttribute(kernC, cudaFuncAttributeMaxDynamicSharedMemorySize, smemC);

    kernA<<<dim3(NCHUNK, B_), 256>>>(x, thw, thb, phw, phb);
    kernB<<<B_, 32>>>(Bp, A);
    kernC<<<dim3(T_ / TT, B_), 128, smemC>>>(x, w1, b1, wr, br, ga, be, rm, rv, out);
}

// round 17
// speedup vs baseline: 1.0514x; 1.0514x over previous
#include <cuda_runtime.h>

#define B_    64
#define CIN   64
#define T_    300
#define N_    25
#define COUT  128
#define EMB   32
#define KV    3
#define NCHUNK 12     // partial-S slices (6 chunks x 2 halves)
#define NPAD  28      // padded joint dim (16B-aligned rows)
#define EW2   130     // kernA interleaved weight row: 2*CIN + pad
#define WP2   258     // kernC interleaved weight row: 2*COUT + pad
#define TT2   10      // t's per kernC block (2 at a time)

typedef unsigned long long u64;

__device__ float g_Spart[B_ * NCHUNK * N_ * N_];
__device__ float g_adj[B_ * N_ * N_];

__device__ __forceinline__ void fma2(u64& d, u64 a, u64 b) {
    asm("fma.rn.f32x2 %0, %1, %2, %0;" : "+l"(d) : "l"(a), "l"(b));
}
__device__ __forceinline__ u64 pack2(float x, float y) {
    u64 r; asm("mov.b64 %0, {%1, %2};" : "=l"(r) : "f"(x), "f"(y)); return r;
}
__device__ __forceinline__ float2 unpack2(u64 v) {
    float2 r; asm("mov.b64 {%0, %1}, %2;" : "=f"(r.x), "=f"(r.y) : "l"(v)); return r;
}
#define BAR(id, cnt) asm volatile("bar.sync %0, %1;" :: "r"(id), "r"(cnt) : "memory")

// ---------------------------------------------------------------------------
// Kernel A: S_b = sum_t Theta_t^T Phi_t  (partial over 50-t chunk, 2 t at once)
// grid (6, B_), 512 threads. Halves run decoupled via named barriers.
// Pipelined: gram(t) overlaps gmem load of x(t+1).
// ---------------------------------------------------------------------------
__global__ __launch_bounds__(512) void kernA(
    const float* __restrict__ x,
    const float* __restrict__ thw, const float* __restrict__ thb,
    const float* __restrict__ phw, const float* __restrict__ phb)
{
    __shared__ __align__(16) float wsh[EMB * EW2];       // {theta,phi} interleaved
    __shared__ float tbs[EMB], pbs[EMB];
    __shared__ __align__(16) float xt[2][CIN * NPAD];
    __shared__ __align__(16) float th[2][EMB * NPAD];
    __shared__ __align__(16) float ph[2][EMB * NPAD];

    const int tid = threadIdx.x;
    const int ci = blockIdx.x, b = blockIdx.y;

    for (int i = tid; i < EMB * CIN; i += 512) {
        int e = i >> 6, c = i & 63;
        wsh[e * EW2 + 2 * c]     = thw[i];
        wsh[e * EW2 + 2 * c + 1] = phw[i];
    }
    if (tid < EMB) { tbs[tid] = thb[tid]; pbs[tid] = phb[tid]; }
    // zero x-tile pads once (loads only touch n < 25)
    for (int i = tid; i < 2 * CIN * NPAD; i += 512) xt[0][i] = 0.f;

    const int half = tid >> 8, ltid = tid & 255;
    const int barid = 1 + half;
    float* xth = xt[half];
    float* thh = th[half];
    float* phh = ph[half];

    const int sn = ltid / 7, sg = ltid % 7;
    const bool sact = ltid < (N_ * 7);     // 175
    const int ee = ltid / 7, eg = ltid % 7;
    const bool eact = ltid < (EMB * 7);    // 224
    u64 s0 = 0, s1 = 0;

    const float* xb = x + (size_t)b * CIN * T_ * N_ + (size_t)(ci * 50 + half) * N_;

    __syncthreads();

    // prologue: load + embed for ti = 0
    {
        const float* xp = xb;
        for (int i = ltid; i < CIN * N_; i += 256) {
            int c = i / N_, n = i - c * N_;
            xth[c * NPAD + n] = xp[c * T_ * N_ + n];
        }
        BAR(barid, 256);
        if (eact) {
            u64 a0 = pack2(tbs[ee], tbs[ee]), a1 = a0;
            u64 p0 = pack2(pbs[ee], pbs[ee]), p1 = p0;
            const float* wr = wsh + ee * EW2;
            #pragma unroll 4
            for (int c = 0; c < CIN; ++c) {
                ulonglong2 xq = *(const ulonglong2*)(xth + c * NPAD + eg * 4);
                float2 w = *(const float2*)(wr + 2 * c);
                u64 wtp = pack2(w.x, w.x), wpp = pack2(w.y, w.y);
                fma2(a0, wtp, xq.x); fma2(a1, wtp, xq.y);
                fma2(p0, wpp, xq.x); fma2(p1, wpp, xq.y);
            }
            ulonglong2 ta; ta.x = a0; ta.y = a1;
            *(ulonglong2*)(thh + ee * NPAD + eg * 4) = ta;
            ulonglong2 pa; pa.x = p0; pa.y = p1;
            *(ulonglong2*)(phh + ee * NPAD + eg * 4) = pa;
        }
        BAR(barid, 256);
    }

    for (int ti = 0; ti < 25; ++ti) {
        // gram(ti) + prefetch x(ti+1)
        if (sact) {
            #pragma unroll 4
            for (int e = 0; e < EMB; ++e) {
                float tv = thh[e * NPAD + sn];
                u64 tp = pack2(tv, tv);
                ulonglong2 pq = *(const ulonglong2*)(phh + e * NPAD + sg * 4);
                fma2(s0, tp, pq.x); fma2(s1, tp, pq.y);
            }
        }
        if (ti < 24) {
            const float* xp = xb + (size_t)(ti + 1) * 2 * N_;
            for (int i = ltid; i < CIN * N_; i += 256) {
                int c = i / N_, n = i - c * N_;
                xth[c * NPAD + n] = xp[c * T_ * N_ + n];
            }
        }
        BAR(barid, 256);
        if (ti < 24) {
            if (eact) {
                u64 a0 = pack2(tbs[ee], tbs[ee]), a1 = a0;
                u64 p0 = pack2(pbs[ee], pbs[ee]), p1 = p0;
                const float* wr = wsh + ee * EW2;
                #pragma unroll 4
                for (int c = 0; c < CIN; ++c) {
                    ulonglong2 xq = *(const ulonglong2*)(xth + c * NPAD + eg * 4);
                    float2 w = *(const float2*)(wr + 2 * c);
                    u64 wtp = pack2(w.x, w.x), wpp = pack2(w.y, w.y);
                    fma2(a0, wtp, xq.x); fma2(a1, wtp, xq.y);
                    fma2(p0, wpp, xq.x); fma2(p1, wpp, xq.y);
                }
                ulonglong2 ta; ta.x = a0; ta.y = a1;
                *(ulonglong2*)(thh + ee * NPAD + eg * 4) = ta;
                ulonglong2 pa; pa.x = p0; pa.y = p1;
                *(ulonglong2*)(phh + ee * NPAD + eg * 4) = pa;
            }
            BAR(barid, 256);
        }
    }

    if (sact) {
        float* dst = g_Spart + ((size_t)(b * NCHUNK + ci * 2 + half) * N_ + sn) * N_;
        float2 v0 = unpack2(s0), v1 = unpack2(s1);
        int m0 = sg * 4;
        dst[m0] = v0.x;
        if (m0 + 1 < N_) dst[m0 + 1] = v0.y;
        if (m0 + 2 < N_) dst[m0 + 2] = v1.x;
        if (m0 + 3 < N_) dst[m0 + 3] = v1.y;
    }
}

// ---------------------------------------------------------------------------
// Kernel B: reduce partials, softmax rows, adj = sum_k(A+B) + KV*softmax
// ---------------------------------------------------------------------------
__global__ void kernB(const float* __restrict__ Bp, const float* __restrict__ A)
{
    const int b = blockIdx.x, n = threadIdx.x;
    if (n >= N_) return;
    float row[N_];
    #pragma unroll
    for (int m = 0; m < N_; ++m) {
        float s = 0.f;
        #pragma unroll
        for (int ci = 0; ci < NCHUNK; ++ci)
            s += g_Spart[((b * NCHUNK + ci) * N_ + n) * N_ + m];
        row[m] = s;
    }
    float mx = row[0];
    #pragma unroll
    for (int m = 1; m < N_; ++m) mx = fmaxf(mx, row[m]);
    float den = 0.f;
    #pragma unroll
    for (int m = 0; m < N_; ++m) { row[m] = expf(row[m] - mx); den += row[m]; }
    float inv = (float)KV / den;
    #pragma unroll
    for (int m = 0; m < N_; ++m) {
        float st = 0.f;
        #pragma unroll
        for (int k = 0; k < KV; ++k)
            st += A[(k * N_ + n) * N_ + m] + Bp[(k * N_ + n) * N_ + m];
        g_adj[(b * N_ + n) * N_ + m] = st + row[m] * inv;
    }
}

// ---------------------------------------------------------------------------
// Kernel C: y = X*adj ; out = relu(BN(W1*y + Wr*x + b))
// grid (T_/TT2, B_), 256 threads = two 128-thread halves (2 t concurrent),
// halves decoupled via named barriers. ~97.5 KB dyn smem -> 2 CTA/SM.
// ---------------------------------------------------------------------------
__global__ __launch_bounds__(256) void kernC(
    const float* __restrict__ x,
    const float* __restrict__ w1, const float* __restrict__ b1,
    const float* __restrict__ wr, const float* __restrict__ br,
    const float* __restrict__ gamma, const float* __restrict__ beta,
    const float* __restrict__ rmean, const float* __restrict__ rvar,
    float* __restrict__ out)
{
    extern __shared__ __align__(16) float sm[];
    float* ws   = sm;                       // CIN*WP2 : {w1,wr} interleaved, [c][2o]
    float* adjs = ws + CIN * WP2;           // N_*NPAD
    float* xs0  = adjs + N_ * NPAD;
    float* xs1  = xs0 + CIN * NPAD;
    float* ys0  = xs1 + CIN * NPAD;
    float* ys1  = ys0 + CIN * NPAD;

    const int tid = threadIdx.x;
    const int b = blockIdx.y;
    const int t0 = blockIdx.x * TT2;
    const int half = tid >> 7, o = tid & 127;
    const int barid = 1 + half;
    float* xsh = half ? xs1 : xs0;
    float* ysh = half ? ys1 : ys0;

    for (int i = tid; i < COUT * CIN; i += 256) {
        int oo = i >> 6, c = i & 63;
        ws[c * WP2 + 2 * oo]     = w1[i];
        ws[c * WP2 + 2 * oo + 1] = wr[i];
    }
    for (int i = tid; i < N_ * NPAD; i += 256) {
        int n = i / NPAD, m = i - n * NPAD;
        adjs[i] = (m < N_) ? g_adj[(b * N_ + n) * N_ + m] : 0.f;
    }
    // zero x-tile pads once
    for (int i = tid; i < 2 * CIN * NPAD; i += 256) xs0[i] = 0.f;

    const float sc = gamma[o] * rsqrtf(rvar[o] + 1e-5f);
    const float sh = beta[o] - rmean[o] * sc;
    const float bias = b1[o] + br[o];
    const u64 bias2 = pack2(bias, bias);
    const float* xb = x + (size_t)b * CIN * T_ * N_;
    __syncthreads();

    for (int it = 0; it < TT2 / 2; ++it) {
        const int t = t0 + 2 * it + half;
        // load x tile (25 of 28 cols; pads stay zero)
        {
            const float* xp = xb + (size_t)t * N_;
            for (int i = o; i < CIN * N_; i += 128) {
                int c = i / N_, n = i - c * N_;
                xsh[c * NPAD + n] = xp[c * T_ * N_ + n];
            }
        }
        BAR(barid, 128);
        // y[c][m] = sum_n x[c][n] * adj[n][m]
        for (int it2 = o; it2 < CIN * 7; it2 += 128) {
            int c = it2 / 7, g = it2 - c * 7;
            u64 a0 = 0, a1 = 0;
            const float* xr = xsh + c * NPAD;
            const float* ar = adjs + g * 4;
            #pragma unroll
            for (int n = 0; n < N_; ++n) {
                float xv = xr[n];
                u64 xp2 = pack2(xv, xv);
                ulonglong2 av = *(const ulonglong2*)(ar + n * NPAD);
                fma2(a0, xp2, av.x); fma2(a1, xp2, av.y);
            }
            ulonglong2 w; w.x = a0; w.y = a1;
            *(ulonglong2*)(ysh + c * NPAD + g * 4) = w;
        }
        BAR(barid, 128);
        // main: 28 m-slots as 14 f32x2 accumulators
        u64 acc[14];
        #pragma unroll
        for (int j = 0; j < 14; ++j) acc[j] = bias2;
        const float* wc = ws + 2 * o;
        #pragma unroll 2
        for (int c = 0; c < CIN; ++c) {
            float2 wv = *(const float2*)(wc + c * WP2);
            u64 wap = pack2(wv.x, wv.x), wbp = pack2(wv.y, wv.y);
            const ulonglong2* yr = (const ulonglong2*)(ysh + c * NPAD);
            const ulonglong2* xr = (const ulonglong2*)(xsh + c * NPAD);
            #pragma unroll
            for (int q = 0; q < 7; ++q) {
                ulonglong2 yv = yr[q];
                ulonglong2 xv = xr[q];
                fma2(acc[2 * q],     wap, yv.x);
                fma2(acc[2 * q + 1], wap, yv.y);
                fma2(acc[2 * q],     wbp, xv.x);
                fma2(acc[2 * q + 1], wbp, xv.y);
            }
        }
        // epilogue: BN + ReLU, direct store (25 scalars, contiguous per thread)
        {
            float* op = out + ((size_t)(b * COUT + o) * T_ + t) * N_;
            #pragma unroll
            for (int j = 0; j < 13; ++j) {
                float2 v = unpack2(acc[j]);
                int m0 = 2 * j;
                op[m0] = fmaxf(fmaf(v.x, sc, sh), 0.f);
                if (m0 + 1 < N_)
                    op[m0 + 1] = fmaxf(fmaf(v.y, sc, sh), 0.f);
            }
        }
        BAR(barid, 128);
    }
}

// ---------------------------------------------------------------------------
extern "C" void kernel_launch(void* const* d_in, const int* in_sizes, int n_in,
                              void* d_out, int out_size)
{
    const float* x   = (const float*)d_in[0];
    const float* thw = (const float*)d_in[1];
    const float* thb = (const float*)d_in[2];
    const float* phw = (const float*)d_in[3];
    const float* phb = (const float*)d_in[4];
    const float* Bp  = (const float*)d_in[5];
    const float* A   = (const float*)d_in[6];
    const float* w1  = (const float*)d_in[7];
    const float* b1  = (const float*)d_in[8];
    const float* wr  = (const float*)d_in[9];
    const float* br  = (const float*)d_in[10];
    const float* ga  = (const float*)d_in[11];
    const float* be  = (const float*)d_in[12];
    const float* rm  = (const float*)d_in[13];
    const float* rv  = (const float*)d_in[14];
    float* out = (float*)d_out;

    const int smemC = (CIN * WP2 + N_ * NPAD + 4 * CIN * NPAD) * (int)sizeof(float);
    cudaFuncSetAttribute(kernC, cudaFuncAttributeMaxDynamicSharedMemorySize, smemC);

    kernA<<<dim3(6, B_), 512>>>(x, thw, thb, phw, phb);
    kernB<<<B_, 32>>>(Bp, A);
    kernC<<<dim3(T_ / TT2, B_), 256, smemC>>>(x, w1, b1, wr, br, ga, be, rm, rv, out);
}